// round 15
// baseline (speedup 1.0000x reference)
#include <cuda_runtime.h>
#include <cuda_bf16.h>
#include <math.h>

#define BATCH 2048
#define NSITE 100
#define DIM   128
#define NORB  400
#define NOCC  50
#define KDET  4

#define TAB_OUT   ((4 + NSITE) * NORB)
#define TAB_BLK   ((TAB_OUT + 255) / 256)     // 163
#define IDX_BLK   ((BATCH + 255) / 256)       // 8

// ---- scratch (static device globals) ----
__device__ float g_TW[4 * NORB];
__device__ float g_PW[NSITE * NORB];
__device__ short g_site[2][BATCH][NOCC];
__device__ unsigned char g_tok[2][BATCH][NOCC];
__device__ float  g_logdet[2][BATCH][KDET];   // log2 |det|
__device__ float  g_sgndet[2][BATCH][KDET];   // -1/0/+1

__device__ const void*  g_cfgp;
__device__ const void*  g_tokp;
__device__ const void*  g_posp;
__device__ const void*  g_Wp;
__device__ const void*  g_biasp;
__device__ int g_is64;
__device__ int g_isbf16;

struct InArgs { const void* p[8]; long long sz[8]; int n; };

__device__ __forceinline__ float ld_f(const void* p, int i, int bf16) {
    if (bf16) return __bfloat162float(((const __nv_bfloat16*)p)[i]);
    return ((const float*)p)[i];
}

// ---------------------------------------------------------------------------
// Warp-parallel content classification of inputs.
__global__ void k_resolve(InArgs a) {
    const unsigned FULL = 0xffffffffu;
    int lane = threadIdx.x;

    bool p64f[8], p32f[8], allzf[8], smallf[8];
    int n = (a.n < 8) ? a.n : 8;

    for (int i = 0; i < n; i++) {
        const unsigned int* w = (const unsigned int*)a.p[i];
        bool p64 = true;
        for (int j = lane; j < 64; j += 32) {
            unsigned lo = w[2 * j], hi = w[2 * j + 1];
            if (lo > 3u || hi != 0u) p64 = false;
        }
        bool p32 = true, allz = true;
        float m = 0.f;
        const float* f = (const float*)a.p[i];
        for (int j = lane; j < 128; j += 32) {
            unsigned v = w[j];
            if (v > 3u) p32 = false;
            if (v != 0u) allz = false;
            m += fabsf(f[j]);
        }
        p64f[i]  = __all_sync(FULL, p64);
        p32f[i]  = __all_sync(FULL, p32);
        allzf[i] = __all_sync(FULL, allz);
#pragma unroll
        for (int off = 16; off; off >>= 1)
            m += __shfl_xor_sync(FULL, m, off);
        smallf[i] = (m * (1.f / 128.f)) < 0.2f;
    }

    if (lane != 0) return;

    int cfgI = -1, biasI = -1, WI = -1;
    int tabI[8]; int ntab = 0;
    int is64 = 0;
    for (int i = 0; i < n; i++) {
        if (allzf[i])            { if (biasI < 0) biasI = i; continue; }
        if (p64f[i] || p32f[i])  { if (cfgI < 0) { cfgI = i; is64 = p64f[i] ? 1 : 0; } continue; }
        if (smallf[i])           { if (WI < 0) WI = i; continue; }
        if (ntab < 8) tabI[ntab++] = i;
    }

    int tokI = -1, posI = -1;
    if (ntab >= 2) {
        int aI = tabI[0], bI = tabI[1];
        if (a.sz[aI] >= a.sz[bI]) { posI = aI; tokI = bI; }
        else                      { posI = bI; tokI = aI; }
    } else if (ntab == 1) { tokI = posI = tabI[0]; }

    if (cfgI  < 0) cfgI  = 0;
    if (tokI  < 0) tokI  = (n > 1) ? 1 : 0;
    if (posI  < 0) posI  = (n > 2) ? 2 : 0;
    if (WI    < 0) WI    = (n > 3) ? 3 : 0;
    if (biasI < 0) biasI = (n > 4) ? 4 : 0;

    int sane = 0;
    const unsigned short* h = (const unsigned short*)a.p[WI];
    for (int j = 0; j < 128; j++) {
        __nv_bfloat16 bl = *(const __nv_bfloat16*)&h[2 * j];
        float v = fabsf(__bfloat162float(bl));
        if (v >= 1e-6f && v <= 1e3f) sane++;
    }
    g_isbf16 = (sane > 64) ? 1 : 0;

    g_cfgp  = a.p[cfgI];
    g_tokp  = a.p[tokI];
    g_posp  = a.p[posI];
    g_Wp    = a.p[WI];
    g_biasp = a.p[biasI];
    g_is64  = is64;
}

// ---------------------------------------------------------------------------
__global__ void k_prep() {
    int bf = g_isbf16;
    if (blockIdx.x < TAB_BLK) {
        int t = blockIdx.x * 256 + threadIdx.x;
        if (t >= TAB_OUT) return;
        int r = t / NORB;
        int o = t - r * NORB;
        int sbase = (r < 4) ? r * DIM : (r - 4) * DIM;
        const void* src = (r < 4) ? g_tokp : g_posp;
        float acc = 0.f;
#pragma unroll 8
        for (int d = 0; d < DIM; d++)
            acc = fmaf(ld_f(src, sbase + d, bf), ld_f(g_Wp, o * DIM + d, bf), acc);
        if (r < 4) g_TW[r * NORB + o] = acc;
        else       g_PW[(r - 4) * NORB + o] = acc + ld_f(g_biasp, o, bf);
        return;
    }

    int b = (blockIdx.x - TAB_BLK) * 256 + threadIdx.x;
    if (b >= BATCH) return;

    unsigned char c[NSITE];
    if (g_is64) {
        const long long* p = (const long long*)g_cfgp + (long long)b * NSITE;
        for (int n = 0; n < NSITE; n++) c[n] = (unsigned char)(p[n] & 3);
    } else {
        const int* p = (const int*)g_cfgp + b * NSITE;
        for (int n = 0; n < NSITE; n++) c[n] = (unsigned char)(p[n] & 3);
    }

    for (int spin = 0; spin < 2; spin++) {
        unsigned char bit = spin ? 2 : 1;
        short lst[NOCC];
        int cnt = 0;
        for (int n = 0; n < NSITE && cnt < NOCC; n++)
            if (c[n] & bit) lst[cnt++] = (short)n;
        int c1 = cnt;
        for (int n = 0; n < NSITE && cnt < NOCC; n++)
            if (!(c[n] & bit)) lst[cnt++] = (short)n;
        int p = 0, q = c1;
        for (int o = 0; o < NOCC; o++) {
            short v;
            bool takep = (p < c1) && (q >= NOCC || lst[p] < lst[q]);
            if (takep) v = lst[p++]; else v = lst[q++];
            g_site[spin][b][o] = v;
            g_tok[spin][b][o]  = c[v];
        }
    }
}

// ---------------------------------------------------------------------------
// 64 threads per det, ONE ROW PER THREAD (rows 50..63 are zero dummies).
// Per step: warp REDUX argmax -> the warp-local winner SPECULATIVELY stores
// its row (incl. col0) + key to its warp's smem slot BEFORE the barrier;
// ONE __syncthreads; all threads pick the winning warp by key and read its
// buffer. Double-buffered (WAR separated by two barriers). Shifted-window
// registers; uniform 64-bit retired mask for parity.
template<int NC>
__device__ __forceinline__ void lu_chunk(
    int steps, float (&a)[NOCC], bool& alive, int row, int wid, int lane,
    unsigned long long& retired, float& lmag, int& inv, int& nneg,
    bool& zerod, float4* ubuf, unsigned* kbuf, int& par)
{
    constexpr int NQ = (NC >> 2) + 1;
    const unsigned FULL = 0xffffffffu;

#pragma unroll 1
    for (int s = 0; s < steps; s++) {
        int bsel = (par ^= 1);
        float4* ubw = ubuf + (bsel * 2 + wid) * 13;

        // ---- per-warp argmax |col0| (key: mag[31:6] | 63-row) ----
        unsigned key = 0u;
        if (alive)
            key = (__float_as_uint(fabsf(a[0])) & 0xFFFFFFC0u) | (unsigned)(63 - row);
        unsigned kw = __reduce_max_sync(FULL, key);
        if (lane == 0) kbuf[bsel * 2 + wid] = kw;

        // warp-local winner speculatively publishes its row (incl. col0)
        if (key == kw && key != 0u) {
#pragma unroll
            for (int q = 0; q < NQ; q++)
                ubw[q] = make_float4(
                    a[4 * q],
                    (4 * q + 1 <= NC) ? a[4 * q + 1] : 0.f,
                    (4 * q + 2 <= NC) ? a[4 * q + 2] : 0.f,
                    (4 * q + 3 <= NC) ? a[4 * q + 3] : 0.f);
        }
        __syncthreads();

        // ---- pick global winner ----
        unsigned k0 = kbuf[bsel * 2 + 0];
        unsigned k1 = kbuf[bsel * 2 + 1];
        int wsel    = (k1 > k0) ? 1 : 0;
        unsigned mx = (k1 > k0) ? k1 : k0;
        int p = 63 - (int)(mx & 63u);          // pivot row, block-uniform
        const float4* us = ubuf + (bsel * 2 + wsel) * 13;

        if (row == p) alive = false;

        // ---- parity from uniform retired mask ----
        unsigned long long above = ~((2ull << p) - 1ull);
        inv += __popcll(retired & above);
        retired |= 1ull << p;

        // ---- update ----
        float4 U0 = us[0];
        float piv = U0.x;
        if (piv == 0.f) zerod = true;
        lmag += log2f(fabsf(piv));
        nneg += (piv < 0.f) ? 1 : 0;

        float ma = a[0] * (-1.0f / piv);   // pivot row -> -1 (self-zeroes);
                                           // retired/dummy rows col0==0 -> 0
        if (1 <= NC) a[0] = fmaf(ma, U0.y, a[1]);
        if (2 <= NC) a[1] = fmaf(ma, U0.z, a[2]);
        if (3 <= NC) a[2] = fmaf(ma, U0.w, a[3]);
#pragma unroll
        for (int q = 1; q < NQ; q++) {
            float4 U = us[q];
            {                      a[4 * q - 1] = fmaf(ma, U.x, a[4 * q]); }
            if (4 * q + 1 <= NC) { a[4 * q]     = fmaf(ma, U.y, a[4 * q + 1]); }
            if (4 * q + 2 <= NC) { a[4 * q + 1] = fmaf(ma, U.z, a[4 * q + 2]); }
            if (4 * q + 3 <= NC) { a[4 * q + 2] = fmaf(ma, U.w, a[4 * q + 3]); }
        }
        // next step uses the other buffer; reuse is two barriers away
    }
}

// ---------------------------------------------------------------------------
__global__ void __launch_bounds__(64, 12) k_main() {
    __shared__ float4 ubuf[2 * 2 * 13];    // [buffer][warp][13]
    __shared__ unsigned kbuf[4];           // [buffer][warp]

    int idx  = blockIdx.x;
    int b    = idx >> 3;
    int rr   = idx & 7;
    int spin = rr >> 2;
    int kk   = rr & 3;
    int tid  = threadIdx.x;
    int wid  = tid >> 5;
    int lane = tid & 31;
    int row  = tid;                         // one row per thread
    bool isreal = (row < NOCC);

    int colbase = spin * 200 + kk * 50;
    int rc = isreal ? row : 0;
    int s0 = g_site[spin][b][rc];
    int t0 = g_tok[spin][b][rc];
    const float* TW0 = g_TW + t0 * NORB + colbase;
    const float* PW0 = g_PW + s0 * NORB + colbase;

    float a[NOCC];
#pragma unroll
    for (int c = 0; c < NOCC; c++) {
        float v = TW0[c] + PW0[c];
        a[c] = isreal ? v : 0.f;
    }

    bool alive = isreal;
    unsigned long long retired = 0ull;
    float lmag = 0.f;
    int   inv  = 0;
    int   nneg = 0;
    bool  zerod = false;
    int   par  = 0;

    lu_chunk<49>(5, a, alive, row, wid, lane, retired, lmag, inv, nneg, zerod, ubuf, kbuf, par);
    lu_chunk<44>(5, a, alive, row, wid, lane, retired, lmag, inv, nneg, zerod, ubuf, kbuf, par);
    lu_chunk<39>(5, a, alive, row, wid, lane, retired, lmag, inv, nneg, zerod, ubuf, kbuf, par);
    lu_chunk<34>(5, a, alive, row, wid, lane, retired, lmag, inv, nneg, zerod, ubuf, kbuf, par);
    lu_chunk<29>(5, a, alive, row, wid, lane, retired, lmag, inv, nneg, zerod, ubuf, kbuf, par);
    lu_chunk<24>(5, a, alive, row, wid, lane, retired, lmag, inv, nneg, zerod, ubuf, kbuf, par);
    lu_chunk<19>(5, a, alive, row, wid, lane, retired, lmag, inv, nneg, zerod, ubuf, kbuf, par);
    lu_chunk<14>(5, a, alive, row, wid, lane, retired, lmag, inv, nneg, zerod, ubuf, kbuf, par);
    lu_chunk<9> (5, a, alive, row, wid, lane, retired, lmag, inv, nneg, zerod, ubuf, kbuf, par);
    lu_chunk<4> (5, a, alive, row, wid, lane, retired, lmag, inv, nneg, zerod, ubuf, kbuf, par);

    if (tid == 0) {
        float sgn = zerod ? 0.f : (((inv + nneg) & 1) ? -1.f : 1.f);
        g_logdet[spin][b][kk] = lmag;
        g_sgndet[spin][b][kk] = sgn;
    }
}

// ---------------------------------------------------------------------------
__global__ void k_combine(float* __restrict__ out, int out_elems) {
    int b = blockIdx.x * blockDim.x + threadIdx.x;
    if (b >= BATCH) return;

    float L[KDET], S[KDET];
    float M = -1e30f;
    for (int k = 0; k < KDET; k++) {
        S[k] = g_sgndet[0][b][k] * g_sgndet[1][b][k];
        L[k] = g_logdet[0][b][k] + g_logdet[1][b][k];
        if (S[k] != 0.f && L[k] > M) M = L[k];
    }
    float psis = 0.f;
    for (int k = 0; k < KDET; k++)
        if (S[k] != 0.f) psis += S[k] * exp2f(L[k] - M);

    double apsi = fabs((double)psis) * exp2((double)M);
    float la = (float)log(apsi + 1e-30);
    float ph = (psis >= 0.f) ? 0.f : 3.14159265358979323846f;

    if (out_elems == BATCH) {
        out[b] = la;
    } else {
        out[2 * b]     = la;
        out[2 * b + 1] = ph;
    }
}

// ---------------------------------------------------------------------------
extern "C" void kernel_launch(void* const* d_in, const int* in_sizes, int n_in,
                              void* d_out, int out_size) {
    InArgs a;
    a.n = (n_in < 8) ? n_in : 8;
    for (int i = 0; i < 8; i++) {
        a.p[i]  = (i < n_in) ? d_in[i] : d_in[0];
        a.sz[i] = (i < n_in) ? (long long)in_sizes[i] : 0;
    }

    k_resolve<<<1, 32>>>(a);
    k_prep   <<<TAB_BLK + IDX_BLK, 256>>>();
    k_main   <<<BATCH * 2 * KDET, 64>>>();
    k_combine<<<IDX_BLK, 256>>>((float*)d_out, out_size);
}

// round 16
// speedup vs baseline: 1.5473x; 1.5473x over previous
#include <cuda_runtime.h>
#include <cuda_bf16.h>
#include <math.h>

#define BATCH 2048
#define NSITE 100
#define DIM   128
#define NORB  400
#define NOCC  50
#define KDET  4

#define TAB_OUT   ((4 + NSITE) * NORB)
#define TAB_BLK   ((TAB_OUT + 255) / 256)     // 163
#define IDX_BLK   ((BATCH + 255) / 256)       // 8

// ---- scratch (static device globals) ----
__device__ float g_TW[4 * NORB];
__device__ float g_PW[NSITE * NORB];
__device__ short g_site[2][BATCH][NOCC];
__device__ unsigned char g_tok[2][BATCH][NOCC];
__device__ float  g_logdet[2][BATCH][KDET];   // log2 |det|
__device__ float  g_sgndet[2][BATCH][KDET];   // -1/0/+1

__device__ const void*  g_cfgp;
__device__ const void*  g_tokp;
__device__ const void*  g_posp;
__device__ const void*  g_Wp;
__device__ const void*  g_biasp;
__device__ int g_is64;
__device__ int g_isbf16;

struct InArgs { const void* p[8]; long long sz[8]; int n; };

__device__ __forceinline__ float ld_f(const void* p, int i, int bf16) {
    if (bf16) return __bfloat162float(((const __nv_bfloat16*)p)[i]);
    return ((const float*)p)[i];
}

// ---------------------------------------------------------------------------
// Warp-parallel content classification of inputs.
__global__ void k_resolve(InArgs a) {
    const unsigned FULL = 0xffffffffu;
    int lane = threadIdx.x;

    bool p64f[8], p32f[8], allzf[8], smallf[8];
    int n = (a.n < 8) ? a.n : 8;

    for (int i = 0; i < n; i++) {
        const unsigned int* w = (const unsigned int*)a.p[i];
        bool p64 = true;
        for (int j = lane; j < 64; j += 32) {
            unsigned lo = w[2 * j], hi = w[2 * j + 1];
            if (lo > 3u || hi != 0u) p64 = false;
        }
        bool p32 = true, allz = true;
        float m = 0.f;
        const float* f = (const float*)a.p[i];
        for (int j = lane; j < 128; j += 32) {
            unsigned v = w[j];
            if (v > 3u) p32 = false;
            if (v != 0u) allz = false;
            m += fabsf(f[j]);
        }
        p64f[i]  = __all_sync(FULL, p64);
        p32f[i]  = __all_sync(FULL, p32);
        allzf[i] = __all_sync(FULL, allz);
#pragma unroll
        for (int off = 16; off; off >>= 1)
            m += __shfl_xor_sync(FULL, m, off);
        smallf[i] = (m * (1.f / 128.f)) < 0.2f;
    }

    if (lane != 0) return;

    int cfgI = -1, biasI = -1, WI = -1;
    int tabI[8]; int ntab = 0;
    int is64 = 0;
    for (int i = 0; i < n; i++) {
        if (allzf[i])            { if (biasI < 0) biasI = i; continue; }
        if (p64f[i] || p32f[i])  { if (cfgI < 0) { cfgI = i; is64 = p64f[i] ? 1 : 0; } continue; }
        if (smallf[i])           { if (WI < 0) WI = i; continue; }
        if (ntab < 8) tabI[ntab++] = i;
    }

    int tokI = -1, posI = -1;
    if (ntab >= 2) {
        int aI = tabI[0], bI = tabI[1];
        if (a.sz[aI] >= a.sz[bI]) { posI = aI; tokI = bI; }
        else                      { posI = bI; tokI = aI; }
    } else if (ntab == 1) { tokI = posI = tabI[0]; }

    if (cfgI  < 0) cfgI  = 0;
    if (tokI  < 0) tokI  = (n > 1) ? 1 : 0;
    if (posI  < 0) posI  = (n > 2) ? 2 : 0;
    if (WI    < 0) WI    = (n > 3) ? 3 : 0;
    if (biasI < 0) biasI = (n > 4) ? 4 : 0;

    int sane = 0;
    const unsigned short* h = (const unsigned short*)a.p[WI];
    for (int j = 0; j < 128; j++) {
        __nv_bfloat16 bl = *(const __nv_bfloat16*)&h[2 * j];
        float v = fabsf(__bfloat162float(bl));
        if (v >= 1e-6f && v <= 1e3f) sane++;
    }
    g_isbf16 = (sane > 64) ? 1 : 0;

    g_cfgp  = a.p[cfgI];
    g_tokp  = a.p[tokI];
    g_posp  = a.p[posI];
    g_Wp    = a.p[WI];
    g_biasp = a.p[biasI];
    g_is64  = is64;
}

// ---------------------------------------------------------------------------
__global__ void k_prep() {
    int bf = g_isbf16;
    if (blockIdx.x < TAB_BLK) {
        int t = blockIdx.x * 256 + threadIdx.x;
        if (t >= TAB_OUT) return;
        int r = t / NORB;
        int o = t - r * NORB;
        int sbase = (r < 4) ? r * DIM : (r - 4) * DIM;
        const void* src = (r < 4) ? g_tokp : g_posp;
        float acc = 0.f;
#pragma unroll 8
        for (int d = 0; d < DIM; d++)
            acc = fmaf(ld_f(src, sbase + d, bf), ld_f(g_Wp, o * DIM + d, bf), acc);
        if (r < 4) g_TW[r * NORB + o] = acc;
        else       g_PW[(r - 4) * NORB + o] = acc + ld_f(g_biasp, o, bf);
        return;
    }

    int b = (blockIdx.x - TAB_BLK) * 256 + threadIdx.x;
    if (b >= BATCH) return;

    unsigned char c[NSITE];
    if (g_is64) {
        const long long* p = (const long long*)g_cfgp + (long long)b * NSITE;
        for (int n = 0; n < NSITE; n++) c[n] = (unsigned char)(p[n] & 3);
    } else {
        const int* p = (const int*)g_cfgp + b * NSITE;
        for (int n = 0; n < NSITE; n++) c[n] = (unsigned char)(p[n] & 3);
    }

    for (int spin = 0; spin < 2; spin++) {
        unsigned char bit = spin ? 2 : 1;
        short lst[NOCC];
        int cnt = 0;
        for (int n = 0; n < NSITE && cnt < NOCC; n++)
            if (c[n] & bit) lst[cnt++] = (short)n;
        int c1 = cnt;
        for (int n = 0; n < NSITE && cnt < NOCC; n++)
            if (!(c[n] & bit)) lst[cnt++] = (short)n;
        int p = 0, q = c1;
        for (int o = 0; o < NOCC; o++) {
            short v;
            bool takep = (p < c1) && (q >= NOCC || lst[p] < lst[q]);
            if (takep) v = lst[p++]; else v = lst[q++];
            g_site[spin][b][o] = v;
            g_tok[spin][b][o]  = c[v];
        }
    }
}

// ---------------------------------------------------------------------------
// GENP LU chunk (NO PIVOT SEARCH): at global step g the pivot row is row g,
// owner lane g&31 (array a if g<32 else bb) — all warp-uniform. Shifted
// window registers, double-buffered smem float4 broadcast, one syncwarp
// per step. Retired rows accumulate garbage that is never read again.
template<int NC>
__device__ __forceinline__ void lu_chunk(
    int steps, int gbase, float (&a)[NOCC], float (&bb)[NOCC], int lane,
    float& lmag, int& nneg, bool& zerod, float4* u4, int& par)
{
    constexpr int NQ = (NC >> 2) + 1;

#pragma unroll 1
    for (int s = 0; s < steps; s++) {
        int g = gbase + s;                 // uniform
        int src = g & 31;
        bool top = (g < 32);
        float4* ub = u4 + ((par ^= 1) ? 13 : 0);

        // ---- pivot owner stores its row INCLUDING col0 ----
        if (top) {
            if (lane == src) {
#pragma unroll
                for (int q = 0; q < NQ; q++)
                    ub[q] = make_float4(
                        a[4 * q],
                        (4 * q + 1 <= NC) ? a[4 * q + 1] : 0.f,
                        (4 * q + 2 <= NC) ? a[4 * q + 2] : 0.f,
                        (4 * q + 3 <= NC) ? a[4 * q + 3] : 0.f);
            }
        } else {
            if (lane == src) {
#pragma unroll
                for (int q = 0; q < NQ; q++)
                    ub[q] = make_float4(
                        bb[4 * q],
                        (4 * q + 1 <= NC) ? bb[4 * q + 1] : 0.f,
                        (4 * q + 2 <= NC) ? bb[4 * q + 2] : 0.f,
                        (4 * q + 3 <= NC) ? bb[4 * q + 3] : 0.f);
            }
        }
        __syncwarp();

        // ---- update ----
        float4 U0 = ub[0];
        float piv = U0.x;
        if (piv == 0.f) zerod = true;
        lmag += log2f(fabsf(piv));
        nneg += (piv < 0.f) ? 1 : 0;

        float ninv = -1.0f / piv;
        float ma = a[0]  * ninv;   // pivot row -> -1 (garbage, retired); ok
        float mb = bb[0] * ninv;   // dummy rows stay 0

        {
            if (1 <= NC) { a[0] = fmaf(ma, U0.y, a[1]); bb[0] = fmaf(mb, U0.y, bb[1]); }
            if (2 <= NC) { a[1] = fmaf(ma, U0.z, a[2]); bb[1] = fmaf(mb, U0.z, bb[2]); }
            if (3 <= NC) { a[2] = fmaf(ma, U0.w, a[3]); bb[2] = fmaf(mb, U0.w, bb[3]); }
        }
#pragma unroll
        for (int q = 1; q < NQ; q++) {
            float4 U = ub[q];
            {                      a[4 * q - 1] = fmaf(ma, U.x, a[4 * q]);
                                   bb[4 * q - 1]= fmaf(mb, U.x, bb[4 * q]); }
            if (4 * q + 1 <= NC) { a[4 * q]     = fmaf(ma, U.y, a[4 * q + 1]);
                                   bb[4 * q]    = fmaf(mb, U.y, bb[4 * q + 1]); }
            if (4 * q + 2 <= NC) { a[4 * q + 1] = fmaf(ma, U.z, a[4 * q + 2]);
                                   bb[4 * q + 1]= fmaf(mb, U.z, bb[4 * q + 2]); }
            if (4 * q + 3 <= NC) { a[4 * q + 2] = fmaf(ma, U.w, a[4 * q + 3]);
                                   bb[4 * q + 2]= fmaf(mb, U.w, bb[4 * q + 3]); }
        }
        // buffer reuse is separated by the next step's syncwarp (double buf)
    }
}

// ---------------------------------------------------------------------------
__global__ void __launch_bounds__(32, 16) k_main() {
    __shared__ float4 ubuf[26];

    int idx  = blockIdx.x;
    int b    = idx >> 3;
    int rr   = idx & 7;
    int spin = rr >> 2;
    int kk   = rr & 3;
    int lane = threadIdx.x;

    int r1 = 32 + lane;
    bool has1 = (lane < 18);

    int colbase = spin * 200 + kk * 50;

    int s0 = g_site[spin][b][lane];
    int t0 = g_tok[spin][b][lane];
    int s1 = has1 ? (int)g_site[spin][b][r1] : 0;
    int t1 = has1 ? (int)g_tok[spin][b][r1] : 0;

    const float* TW0 = g_TW + t0 * NORB + colbase;
    const float* PW0 = g_PW + s0 * NORB + colbase;
    const float* TW1 = g_TW + t1 * NORB + colbase;
    const float* PW1 = g_PW + s1 * NORB + colbase;

    float a[NOCC], bb[NOCC];
#pragma unroll
    for (int c = 0; c < NOCC; c++) {
        a[c] = TW0[c] + PW0[c];
        float v1 = TW1[c] + PW1[c];
        bb[c] = has1 ? v1 : 0.f;
    }

    float lmag = 0.f;
    int   nneg = 0;
    bool  zerod = false;
    int   par  = 0;

    lu_chunk<49>(5,  0, a, bb, lane, lmag, nneg, zerod, ubuf, par);
    lu_chunk<44>(5,  5, a, bb, lane, lmag, nneg, zerod, ubuf, par);
    lu_chunk<39>(5, 10, a, bb, lane, lmag, nneg, zerod, ubuf, par);
    lu_chunk<34>(5, 15, a, bb, lane, lmag, nneg, zerod, ubuf, par);
    lu_chunk<29>(5, 20, a, bb, lane, lmag, nneg, zerod, ubuf, par);
    lu_chunk<24>(5, 25, a, bb, lane, lmag, nneg, zerod, ubuf, par);
    lu_chunk<19>(5, 30, a, bb, lane, lmag, nneg, zerod, ubuf, par);
    lu_chunk<14>(5, 35, a, bb, lane, lmag, nneg, zerod, ubuf, par);
    lu_chunk<9> (5, 40, a, bb, lane, lmag, nneg, zerod, ubuf, par);
    lu_chunk<4> (5, 45, a, bb, lane, lmag, nneg, zerod, ubuf, par);

    if (lane == 0) {
        float sgn = zerod ? 0.f : ((nneg & 1) ? -1.f : 1.f);
        g_logdet[spin][b][kk] = lmag;
        g_sgndet[spin][b][kk] = sgn;
    }
}

// ---------------------------------------------------------------------------
__global__ void k_combine(float* __restrict__ out, int out_elems) {
    int b = blockIdx.x * blockDim.x + threadIdx.x;
    if (b >= BATCH) return;

    float L[KDET], S[KDET];
    float M = -1e30f;
    for (int k = 0; k < KDET; k++) {
        S[k] = g_sgndet[0][b][k] * g_sgndet[1][b][k];
        L[k] = g_logdet[0][b][k] + g_logdet[1][b][k];
        if (S[k] != 0.f && L[k] > M) M = L[k];
    }
    float psis = 0.f;
    for (int k = 0; k < KDET; k++)
        if (S[k] != 0.f) psis += S[k] * exp2f(L[k] - M);

    double apsi = fabs((double)psis) * exp2((double)M);
    float la = (float)log(apsi + 1e-30);
    float ph = (psis >= 0.f) ? 0.f : 3.14159265358979323846f;

    if (out_elems == BATCH) {
        out[b] = la;
    } else {
        out[2 * b]     = la;
        out[2 * b + 1] = ph;
    }
}

// ---------------------------------------------------------------------------
extern "C" void kernel_launch(void* const* d_in, const int* in_sizes, int n_in,
                              void* d_out, int out_size) {
    InArgs a;
    a.n = (n_in < 8) ? n_in : 8;
    for (int i = 0; i < 8; i++) {
        a.p[i]  = (i < n_in) ? d_in[i] : d_in[0];
        a.sz[i] = (i < n_in) ? (long long)in_sizes[i] : 0;
    }

    k_resolve<<<1, 32>>>(a);
    k_prep   <<<TAB_BLK + IDX_BLK, 256>>>();
    k_main   <<<BATCH * 2 * KDET, 32>>>();
    k_combine<<<IDX_BLK, 256>>>((float*)d_out, out_size);
}

// round 17
// speedup vs baseline: 1.5705x; 1.0150x over previous
#include <cuda_runtime.h>
#include <cuda_bf16.h>
#include <math.h>

#define BATCH 2048
#define NSITE 100
#define DIM   128
#define NORB  400
#define NOCC  50
#define KDET  4

#define TAB_OUT   ((4 + NSITE) * NORB)
#define TAB_BLK   ((TAB_OUT + 255) / 256)     // 163
#define IDX_BLK   ((BATCH + 255) / 256)       // 8

// ---- scratch (static device globals) ----
__device__ float g_TW[4 * NORB];
__device__ float g_PW[NSITE * NORB];
__device__ short g_site[2][BATCH][NOCC];
__device__ unsigned char g_tok[2][BATCH][NOCC];
__device__ float  g_logdet[2][BATCH][KDET];   // log2 |det|
__device__ float  g_sgndet[2][BATCH][KDET];   // -1/0/+1

__device__ const void*  g_cfgp;
__device__ const void*  g_tokp;
__device__ const void*  g_posp;
__device__ const void*  g_Wp;
__device__ const void*  g_biasp;
__device__ int g_is64;
__device__ int g_isbf16;

struct InArgs { const void* p[8]; long long sz[8]; int n; };

__device__ __forceinline__ float ld_f(const void* p, int i, int bf16) {
    if (bf16) return __bfloat162float(((const __nv_bfloat16*)p)[i]);
    return ((const float*)p)[i];
}

__device__ __forceinline__ float frcp_ap(float x) {
    float r;
    asm("rcp.approx.f32 %0, %1;" : "=f"(r) : "f"(x));
    return r;
}

// ---------------------------------------------------------------------------
// Warp-parallel content classification of inputs.
__global__ void k_resolve(InArgs a) {
    const unsigned FULL = 0xffffffffu;
    int lane = threadIdx.x;

    bool p64f[8], p32f[8], allzf[8], smallf[8];
    int n = (a.n < 8) ? a.n : 8;

    for (int i = 0; i < n; i++) {
        const unsigned int* w = (const unsigned int*)a.p[i];
        bool p64 = true;
        for (int j = lane; j < 64; j += 32) {
            unsigned lo = w[2 * j], hi = w[2 * j + 1];
            if (lo > 3u || hi != 0u) p64 = false;
        }
        bool p32 = true, allz = true;
        float m = 0.f;
        const float* f = (const float*)a.p[i];
        for (int j = lane; j < 128; j += 32) {
            unsigned v = w[j];
            if (v > 3u) p32 = false;
            if (v != 0u) allz = false;
            m += fabsf(f[j]);
        }
        p64f[i]  = __all_sync(FULL, p64);
        p32f[i]  = __all_sync(FULL, p32);
        allzf[i] = __all_sync(FULL, allz);
#pragma unroll
        for (int off = 16; off; off >>= 1)
            m += __shfl_xor_sync(FULL, m, off);
        smallf[i] = (m * (1.f / 128.f)) < 0.2f;
    }

    if (lane != 0) return;

    int cfgI = -1, biasI = -1, WI = -1;
    int tabI[8]; int ntab = 0;
    int is64 = 0;
    for (int i = 0; i < n; i++) {
        if (allzf[i])            { if (biasI < 0) biasI = i; continue; }
        if (p64f[i] || p32f[i])  { if (cfgI < 0) { cfgI = i; is64 = p64f[i] ? 1 : 0; } continue; }
        if (smallf[i])           { if (WI < 0) WI = i; continue; }
        if (ntab < 8) tabI[ntab++] = i;
    }

    int tokI = -1, posI = -1;
    if (ntab >= 2) {
        int aI = tabI[0], bI = tabI[1];
        if (a.sz[aI] >= a.sz[bI]) { posI = aI; tokI = bI; }
        else                      { posI = bI; tokI = aI; }
    } else if (ntab == 1) { tokI = posI = tabI[0]; }

    if (cfgI  < 0) cfgI  = 0;
    if (tokI  < 0) tokI  = (n > 1) ? 1 : 0;
    if (posI  < 0) posI  = (n > 2) ? 2 : 0;
    if (WI    < 0) WI    = (n > 3) ? 3 : 0;
    if (biasI < 0) biasI = (n > 4) ? 4 : 0;

    int sane = 0;
    const unsigned short* h = (const unsigned short*)a.p[WI];
    for (int j = 0; j < 128; j++) {
        __nv_bfloat16 bl = *(const __nv_bfloat16*)&h[2 * j];
        float v = fabsf(__bfloat162float(bl));
        if (v >= 1e-6f && v <= 1e3f) sane++;
    }
    g_isbf16 = (sane > 64) ? 1 : 0;

    g_cfgp  = a.p[cfgI];
    g_tokp  = a.p[tokI];
    g_posp  = a.p[posI];
    g_Wp    = a.p[WI];
    g_biasp = a.p[biasI];
    g_is64  = is64;
}

// ---------------------------------------------------------------------------
__global__ void k_prep() {
    int bf = g_isbf16;
    if (blockIdx.x < TAB_BLK) {
        int t = blockIdx.x * 256 + threadIdx.x;
        if (t >= TAB_OUT) return;
        int r = t / NORB;
        int o = t - r * NORB;
        int sbase = (r < 4) ? r * DIM : (r - 4) * DIM;
        const void* src = (r < 4) ? g_tokp : g_posp;
        float acc = 0.f;
#pragma unroll 8
        for (int d = 0; d < DIM; d++)
            acc = fmaf(ld_f(src, sbase + d, bf), ld_f(g_Wp, o * DIM + d, bf), acc);
        if (r < 4) g_TW[r * NORB + o] = acc;
        else       g_PW[(r - 4) * NORB + o] = acc + ld_f(g_biasp, o, bf);
        return;
    }

    int b = (blockIdx.x - TAB_BLK) * 256 + threadIdx.x;
    if (b >= BATCH) return;

    unsigned char c[NSITE];
    if (g_is64) {
        const long long* p = (const long long*)g_cfgp + (long long)b * NSITE;
        for (int n = 0; n < NSITE; n++) c[n] = (unsigned char)(p[n] & 3);
    } else {
        const int* p = (const int*)g_cfgp + b * NSITE;
        for (int n = 0; n < NSITE; n++) c[n] = (unsigned char)(p[n] & 3);
    }

    for (int spin = 0; spin < 2; spin++) {
        unsigned char bit = spin ? 2 : 1;
        short lst[NOCC];
        int cnt = 0;
        for (int n = 0; n < NSITE && cnt < NOCC; n++)
            if (c[n] & bit) lst[cnt++] = (short)n;
        int c1 = cnt;
        for (int n = 0; n < NSITE && cnt < NOCC; n++)
            if (!(c[n] & bit)) lst[cnt++] = (short)n;
        int p = 0, q = c1;
        for (int o = 0; o < NOCC; o++) {
            short v;
            bool takep = (p < c1) && (q >= NOCC || lst[p] < lst[q]);
            if (takep) v = lst[p++]; else v = lst[q++];
            g_site[spin][b][o] = v;
            g_tok[spin][b][o]  = c[v];
        }
    }
}

// ---------------------------------------------------------------------------
// RANK-2 GENP LU chunk: each phase retires pivots g=gbase+2s and g+1.
// Row g is published as-is (U); row g+1 is published RAW (V) — every lane
// derives the updated second pivot locally via mV = V0*(-1/piv1).
// Fused double-shift update: a[c-2] = a[c] + alpha*U[c] + beta*V[c].
// One store phase + one syncwarp + one log2f per TWO columns.
template<int NC>
__device__ __forceinline__ void lu2_chunk(
    int phases, int gbase, float (&a)[NOCC], float (&bb)[NOCC], int lane,
    float& lmag, int& nneg, bool& zerod, float4* u4, int& par)
{
    constexpr int NQ = (NC >> 2) + 1;

#pragma unroll 1
    for (int s = 0; s < phases; s++) {
        int g   = gbase + 2 * s;           // uniform
        int srcU = g & 31;       bool topU = (g < 32);
        int srcV = (g + 1) & 31; bool topV = (g + 1 < 32);

        float4* ub = u4 + ((par ^= 1) ? 26 : 0);
        float4* vb = ub + 13;

        // ---- publish pivot row g (current) and row g+1 (raw) ----
        if (topU) {
            if (lane == srcU) {
#pragma unroll
                for (int q = 0; q < NQ; q++)
                    ub[q] = make_float4(
                        a[4 * q],
                        (4 * q + 1 <= NC) ? a[4 * q + 1] : 0.f,
                        (4 * q + 2 <= NC) ? a[4 * q + 2] : 0.f,
                        (4 * q + 3 <= NC) ? a[4 * q + 3] : 0.f);
            }
        } else {
            if (lane == srcU) {
#pragma unroll
                for (int q = 0; q < NQ; q++)
                    ub[q] = make_float4(
                        bb[4 * q],
                        (4 * q + 1 <= NC) ? bb[4 * q + 1] : 0.f,
                        (4 * q + 2 <= NC) ? bb[4 * q + 2] : 0.f,
                        (4 * q + 3 <= NC) ? bb[4 * q + 3] : 0.f);
            }
        }
        if (topV) {
            if (lane == srcV) {
#pragma unroll
                for (int q = 0; q < NQ; q++)
                    vb[q] = make_float4(
                        a[4 * q],
                        (4 * q + 1 <= NC) ? a[4 * q + 1] : 0.f,
                        (4 * q + 2 <= NC) ? a[4 * q + 2] : 0.f,
                        (4 * q + 3 <= NC) ? a[4 * q + 3] : 0.f);
            }
        } else {
            if (lane == srcV) {
#pragma unroll
                for (int q = 0; q < NQ; q++)
                    vb[q] = make_float4(
                        bb[4 * q],
                        (4 * q + 1 <= NC) ? bb[4 * q + 1] : 0.f,
                        (4 * q + 2 <= NC) ? bb[4 * q + 2] : 0.f,
                        (4 * q + 3 <= NC) ? bb[4 * q + 3] : 0.f);
            }
        }
        __syncwarp();

        float4 U0 = ub[0], V0 = vb[0];
        float piv1  = U0.x;
        float ninv1 = -frcp_ap(piv1);
        float mV    = V0.x * ninv1;
        float piv2  = fmaf(mV, U0.y, V0.y);
        float ninv2 = -frcp_ap(piv2);

        float pp = piv1 * piv2;
        if (pp == 0.f) zerod = true;
        lmag += log2f(fabsf(pp));
        nneg += (pp < 0.f) ? 1 : 0;

        // per-row rank-2 coefficients (dead/dummy rows: cols 0,1 == 0 -> 0)
        float m1a = a[0] * ninv1;
        float m2a = fmaf(m1a, U0.y, a[1]) * ninv2;
        float alA = fmaf(m2a, mV, m1a);

        float m1b = bb[0] * ninv1;
        float m2b = fmaf(m1b, U0.y, bb[1]) * ninv2;
        float alB = fmaf(m2b, mV, m1b);

        // ---- fused shift-by-2 update: c = 2..NC ----
        if (2 <= NC) { a[0]  = fmaf(alA, U0.z, fmaf(m2a, V0.z, a[2]));
                       bb[0] = fmaf(alB, U0.z, fmaf(m2b, V0.z, bb[2])); }
        if (3 <= NC) { a[1]  = fmaf(alA, U0.w, fmaf(m2a, V0.w, a[3]));
                       bb[1] = fmaf(alB, U0.w, fmaf(m2b, V0.w, bb[3])); }
#pragma unroll
        for (int q = 1; q < NQ; q++) {
            float4 U = ub[q], V = vb[q];
            if (4 * q     <= NC) { a[4 * q - 2] = fmaf(alA, U.x, fmaf(m2a, V.x, a[4 * q]));
                                   bb[4 * q - 2]= fmaf(alB, U.x, fmaf(m2b, V.x, bb[4 * q])); }
            if (4 * q + 1 <= NC) { a[4 * q - 1] = fmaf(alA, U.y, fmaf(m2a, V.y, a[4 * q + 1]));
                                   bb[4 * q - 1]= fmaf(alB, U.y, fmaf(m2b, V.y, bb[4 * q + 1])); }
            if (4 * q + 2 <= NC) { a[4 * q]     = fmaf(alA, U.z, fmaf(m2a, V.z, a[4 * q + 2]));
                                   bb[4 * q]    = fmaf(alB, U.z, fmaf(m2b, V.z, bb[4 * q + 2])); }
            if (4 * q + 3 <= NC) { a[4 * q + 1] = fmaf(alA, U.w, fmaf(m2a, V.w, a[4 * q + 3]));
                                   bb[4 * q + 1]= fmaf(alB, U.w, fmaf(m2b, V.w, bb[4 * q + 3])); }
        }
        // buffer reuse is separated by the next phase's syncwarp (double buf)
    }
}

// ---------------------------------------------------------------------------
__global__ void __launch_bounds__(32, 16) k_main() {
    __shared__ float4 ubuf[52];   // [2 buffers][2 rows][13 float4]

    int idx  = blockIdx.x;
    int b    = idx >> 3;
    int rr   = idx & 7;
    int spin = rr >> 2;
    int kk   = rr & 3;
    int lane = threadIdx.x;

    int r1 = 32 + lane;
    bool has1 = (lane < 18);

    int colbase = spin * 200 + kk * 50;

    int s0 = g_site[spin][b][lane];
    int t0 = g_tok[spin][b][lane];
    int s1 = has1 ? (int)g_site[spin][b][r1] : 0;
    int t1 = has1 ? (int)g_tok[spin][b][r1] : 0;

    const float* TW0 = g_TW + t0 * NORB + colbase;
    const float* PW0 = g_PW + s0 * NORB + colbase;
    const float* TW1 = g_TW + t1 * NORB + colbase;
    const float* PW1 = g_PW + s1 * NORB + colbase;

    float a[NOCC], bb[NOCC];
#pragma unroll
    for (int c = 0; c < NOCC; c++) {
        a[c] = TW0[c] + PW0[c];
        float v1 = TW1[c] + PW1[c];
        bb[c] = has1 ? v1 : 0.f;
    }

    float lmag = 0.f;
    int   nneg = 0;
    bool  zerod = false;
    int   par  = 0;

    // 25 rank-2 phases = 50 pivots; window bound shrinks 49/39/29/19/9.
    lu2_chunk<49>(5,  0, a, bb, lane, lmag, nneg, zerod, ubuf, par);
    lu2_chunk<39>(5, 10, a, bb, lane, lmag, nneg, zerod, ubuf, par);
    lu2_chunk<29>(5, 20, a, bb, lane, lmag, nneg, zerod, ubuf, par);
    lu2_chunk<19>(5, 30, a, bb, lane, lmag, nneg, zerod, ubuf, par);
    lu2_chunk<9> (5, 40, a, bb, lane, lmag, nneg, zerod, ubuf, par);

    if (lane == 0) {
        float sgn = zerod ? 0.f : ((nneg & 1) ? -1.f : 1.f);
        g_logdet[spin][b][kk] = lmag;
        g_sgndet[spin][b][kk] = sgn;
    }
}

// ---------------------------------------------------------------------------
__global__ void k_combine(float* __restrict__ out, int out_elems) {
    int b = blockIdx.x * blockDim.x + threadIdx.x;
    if (b >= BATCH) return;

    float L[KDET], S[KDET];
    float M = -1e30f;
    for (int k = 0; k < KDET; k++) {
        S[k] = g_sgndet[0][b][k] * g_sgndet[1][b][k];
        L[k] = g_logdet[0][b][k] + g_logdet[1][b][k];
        if (S[k] != 0.f && L[k] > M) M = L[k];
    }
    float psis = 0.f;
    for (int k = 0; k < KDET; k++)
        if (S[k] != 0.f) psis += S[k] * exp2f(L[k] - M);

    double apsi = fabs((double)psis) * exp2((double)M);
    float la = (float)log(apsi + 1e-30);
    float ph = (psis >= 0.f) ? 0.f : 3.14159265358979323846f;

    if (out_elems == BATCH) {
        out[b] = la;
    } else {
        out[2 * b]     = la;
        out[2 * b + 1] = ph;
    }
}

// ---------------------------------------------------------------------------
extern "C" void kernel_launch(void* const* d_in, const int* in_sizes, int n_in,
                              void* d_out, int out_size) {
    InArgs a;
    a.n = (n_in < 8) ? n_in : 8;
    for (int i = 0; i < 8; i++) {
        a.p[i]  = (i < n_in) ? d_in[i] : d_in[0];
        a.sz[i] = (i < n_in) ? (long long)in_sizes[i] : 0;
    }

    k_resolve<<<1, 32>>>(a);
    k_prep   <<<TAB_BLK + IDX_BLK, 256>>>();
    k_main   <<<BATCH * 2 * KDET, 32>>>();
    k_combine<<<IDX_BLK, 256>>>((float*)d_out, out_size);
}